// round 5
// baseline (speedup 1.0000x reference)
#include <cuda_runtime.h>
#include <cstdint>

// ---------------------------------------------------------------------------
// DeepLagrangianNetwork forward on GB300, fp32 with packed f32x2 FMA.
//
// Pipeline (B = 8192, WIDTH = 1024, N_DOF = 7):
//   Z[b, r, :]  r=0: activations y;  r=1..7: dy/dq_{r-1}   (group of 8 rows)
//   1) layer1:   Z0 = relu(state@W_in+b) and d1 = gate * W_in^T      (cheap)
//   2) gemm x2:  Z_{k+1} = epilogue(Z_k @ W_h)   fused bias/relu/gate
//   3) proj:     P = Z3 @ [W_g | W_ld | W_lo]    (65536 x 29)
//   4) assemble: per-sample 7x7 Lagrangian algebra -> tau, M, C, G
// ---------------------------------------------------------------------------

#define N_DOF   7
#define WIDTH   1024
#define LSIZE   28
#define EPSR    1e-5f

// Scratch (module-load allocated, legal per harness rules).
__device__ float g_Z0[65536 * 1024];      // 256 MB
__device__ float g_Z1[65536 * 1024];      // 256 MB
__device__ float g_P [8192 * 8 * 32];     // 8 MB (29 cols padded to 32)

typedef unsigned long long ull;

// ---- packed f32x2 helpers (Blackwell) -------------------------------------
__device__ __forceinline__ ull dup2(float a) {
    ull r;
    asm("mov.b64 %0, {%1, %1};" : "=l"(r) : "f"(a));
    return r;
}
__device__ __forceinline__ void fma2(ull &d, ull a, ull b) {
    asm("fma.rn.f32x2 %0, %1, %2, %0;" : "+l"(d) : "l"(a), "l"(b));
}
__device__ __forceinline__ float2 unpack2(ull v) {
    float2 r;
    asm("mov.b64 {%0, %1}, %2;" : "=f"(r.x), "=f"(r.y) : "l"(v));
    return r;
}

// ---------------------------------------------------------------------------
// Kernel 1: input layer.  Z[(b*8+0), o] = relu(a),  Z[(b*8+1+d), o] = g*W_in[d,o]
// ---------------------------------------------------------------------------
__global__ void __launch_bounds__(256)
layer1_kernel(const float* __restrict__ state,
              const float* __restrict__ W_in,
              const float* __restrict__ b_in,
              float* __restrict__ Z, int B)
{
    int g = blockIdx.x * blockDim.x + threadIdx.x;
    if (g >= B * WIDTH) return;
    int b = g >> 10;
    int o = g & (WIDTH - 1);

    float a = b_in[o];
    float wv[N_DOF];
#pragma unroll
    for (int i = 0; i < N_DOF; i++) {
        wv[i] = W_in[i * WIDTH + o];
        a = fmaf(state[b * N_DOF + i], wv[i], a);
    }
    size_t base = ((size_t)b * 8) * WIDTH + o;
    Z[base] = fmaxf(a, 0.f);
    float gate = (a > 0.f) ? 1.f : 0.f;
#pragma unroll
    for (int d = 0; d < N_DOF; d++)
        Z[base + (size_t)(1 + d) * WIDTH] = gate * wv[d];
}

// ---------------------------------------------------------------------------
// Kernel 2: fused hidden-layer GEMM.  Zout = epilogue(Zin @ W_h).
// BM=BN=128, BK=16, 256 threads, 8x8 micro-tile with f32x2 packed FMAs.
// Each thread's 8 rows are exactly one sample group -> thread-local gating.
// ---------------------------------------------------------------------------
__global__ void __launch_bounds__(256, 2)
gemm_fused_kernel(const float* __restrict__ Zin,
                  const float* __restrict__ W,
                  const float* __restrict__ bias,
                  float* __restrict__ Zout, int Mrows)
{
    __shared__ __align__(16) float As[16][128];   // As[k][m] (transposed)
    __shared__ __align__(16) float Bs[16][128];   // Bs[k][n]

    const int tid = threadIdx.x;
    const int tr  = tid >> 4;        // 0..15 (row slot: one sample group)
    const int tc  = tid & 15;        // 0..15 (col slot)
    const int rowBase = blockIdx.y * 128;
    const int colBase = blockIdx.x * 128;

    ull acc[8][4];
#pragma unroll
    for (int i = 0; i < 8; i++)
#pragma unroll
        for (int j = 0; j < 4; j++) acc[i][j] = 0ull;

    for (int kt = 0; kt < WIDTH; kt += 16) {
        // --- load A tile (128 x 16) transposed into As[k][m]
#pragma unroll
        for (int t = 0; t < 2; t++) {
            int lin = tid + 256 * t;
            int r   = lin >> 2;          // 0..127
            int c4  = (lin & 3) * 4;     // 0,4,8,12
            int grow = rowBase + r;
            float4 v = make_float4(0.f, 0.f, 0.f, 0.f);
            if (grow < Mrows)
                v = *reinterpret_cast<const float4*>(&Zin[(size_t)grow * WIDTH + kt + c4]);
            As[c4 + 0][r] = v.x;
            As[c4 + 1][r] = v.y;
            As[c4 + 2][r] = v.z;
            As[c4 + 3][r] = v.w;
        }
        // --- load B tile (16 x 128)
#pragma unroll
        for (int t = 0; t < 2; t++) {
            int lin = tid + 256 * t;
            int r   = lin >> 5;          // 0..15
            int c   = (lin & 31) * 4;    // 0..124
            *reinterpret_cast<float4*>(&Bs[r][c]) =
                *reinterpret_cast<const float4*>(&W[(size_t)(kt + r) * WIDTH + colBase + c]);
        }
        __syncthreads();

#pragma unroll
        for (int kk = 0; kk < 16; kk++) {
            float4 a0 = *reinterpret_cast<const float4*>(&As[kk][tr * 8]);
            float4 a1 = *reinterpret_cast<const float4*>(&As[kk][tr * 8 + 4]);
            const ull* bp = reinterpret_cast<const ull*>(&Bs[kk][tc * 8]);
            ull b0 = bp[0], b1 = bp[1], b2 = bp[2], b3 = bp[3];
            ull A2[8] = { dup2(a0.x), dup2(a0.y), dup2(a0.z), dup2(a0.w),
                          dup2(a1.x), dup2(a1.y), dup2(a1.z), dup2(a1.w) };
#pragma unroll
            for (int i = 0; i < 8; i++) {
                fma2(acc[i][0], A2[i], b0);
                fma2(acc[i][1], A2[i], b1);
                fma2(acc[i][2], A2[i], b2);
                fma2(acc[i][3], A2[i], b3);
            }
        }
        __syncthreads();
    }

    // --- epilogue: bias+relu on row 0, gate rows 1..7 with row-0 sign
    const int grow0 = rowBase + tr * 8;
    const int col0  = colBase + tc * 8;
    if (grow0 >= Mrows) return;

    float yv[8], gv[8];
#pragma unroll
    for (int j2 = 0; j2 < 4; j2++) {
        float2 f = unpack2(acc[0][j2]);
        float a0 = f.x + bias[col0 + 2 * j2];
        float a1 = f.y + bias[col0 + 2 * j2 + 1];
        yv[2 * j2]     = fmaxf(a0, 0.f);
        yv[2 * j2 + 1] = fmaxf(a1, 0.f);
        gv[2 * j2]     = (a0 > 0.f) ? 1.f : 0.f;
        gv[2 * j2 + 1] = (a1 > 0.f) ? 1.f : 0.f;
    }
    {
        float4* p = reinterpret_cast<float4*>(&Zout[(size_t)grow0 * WIDTH + col0]);
        p[0] = make_float4(yv[0], yv[1], yv[2], yv[3]);
        p[1] = make_float4(yv[4], yv[5], yv[6], yv[7]);
    }
#pragma unroll
    for (int r = 1; r < 8; r++) {
        float ov[8];
#pragma unroll
        for (int j2 = 0; j2 < 4; j2++) {
            float2 f = unpack2(acc[r][j2]);
            ov[2 * j2]     = gv[2 * j2]     * f.x;
            ov[2 * j2 + 1] = gv[2 * j2 + 1] * f.y;
        }
        float4* p = reinterpret_cast<float4*>(&Zout[(size_t)(grow0 + r) * WIDTH + col0]);
        p[0] = make_float4(ov[0], ov[1], ov[2], ov[3]);
        p[1] = make_float4(ov[4], ov[5], ov[6], ov[7]);
    }
}

// ---------------------------------------------------------------------------
// Kernel 3: head projection.  P[row, 0..28] = Z3[row,:] @ [W_g | W_ld | W_lo]
// (raw projections, no bias — biases applied in assemble).
// ---------------------------------------------------------------------------
__global__ void __launch_bounds__(256)
proj_kernel(const float* __restrict__ Z,
            const float* __restrict__ Wg,
            const float* __restrict__ Wld,
            const float* __restrict__ Wlo,
            float* __restrict__ P, int Mrows)
{
    __shared__ float Zs[64][33];
    __shared__ float Ws[32][32];

    const int tid = threadIdx.x;
    const int rs  = tid >> 5;     // 0..7 row slot (8 rows each)
    const int c   = tid & 31;     // 0..31 col
    const int rowBase = blockIdx.x * 64;

    float acc[8];
#pragma unroll
    for (int j = 0; j < 8; j++) acc[j] = 0.f;

    for (int k0 = 0; k0 < WIDTH; k0 += 32) {
#pragma unroll
        for (int t = 0; t < 8; t++) {
            int lin = tid + 256 * t;
            int r   = lin >> 5;
            int cc  = lin & 31;
            int grow = rowBase + r;
            Zs[r][cc] = (grow < Mrows) ? Z[(size_t)grow * WIDTH + k0 + cc] : 0.f;
        }
#pragma unroll
        for (int t = 0; t < 4; t++) {
            int k  = (tid >> 5) + 8 * t;
            int kk = k0 + k;
            float wv;
            if (c == 0)       wv = Wg[kk];
            else if (c < 8)   wv = Wld[kk * 7 + (c - 1)];
            else if (c < 29)  wv = Wlo[kk * 21 + (c - 8)];
            else              wv = 0.f;
            Ws[k][c] = wv;
        }
        __syncthreads();
#pragma unroll
        for (int kk = 0; kk < 32; kk++) {
            float wv = Ws[kk][c];
#pragma unroll
            for (int j = 0; j < 8; j++)
                acc[j] = fmaf(Zs[rs * 8 + j][kk], wv, acc[j]);
        }
        __syncthreads();
    }

    if (c < 29) {
#pragma unroll
        for (int j = 0; j < 8; j++) {
            int grow = rowBase + rs * 8 + j;
            if (grow < Mrows) P[(size_t)grow * 32 + c] = acc[j];
        }
    }
}

// ---------------------------------------------------------------------------
// Kernel 4: per-sample Lagrangian assembly.
// Key algebraic reductions (no 7x7x7 tensor ever materialized):
//   w = L^T v;  quad_dq[d] = 2 * sum_i der_l[i,d] * v[R[i]] * w[C[i]]
//   dMdt@v = L (dLdt^T v) + dLdt (L^T v)
//   M@a    = L (L^T a) + eps*a
// Output layout (tuple flattened): tau [B,7] | M [B,7,7] | C [B,7] | G [B,7]
// ---------------------------------------------------------------------------
__global__ void __launch_bounds__(256)
assemble_kernel(const float* __restrict__ P,
                const float* __restrict__ vel,
                const float* __restrict__ accel,
                const float* __restrict__ b_ld,
                const float* __restrict__ b_lo,
                float* __restrict__ out, int B)
{
    int b = blockIdx.x * blockDim.x + threadIdx.x;
    if (b >= B) return;

    constexpr int R[28] = {0,1,2,3,4,5,6, 1,2,3,4,5,6, 2,3,4,5,6, 3,4,5,6, 4,5,6, 5,6, 6};
    constexpr int Cc[28]= {0,1,2,3,4,5,6, 0,1,2,3,4,5, 0,1,2,3,4, 0,1,2,3, 0,1,2, 0,1, 0};

    const float* Pb = P + (size_t)b * 256;   // 8 rows x 32 cols

    float v[7], ac[7];
#pragma unroll
    for (int d = 0; d < 7; d++) { v[d] = vel[b * 7 + d]; ac[d] = accel[b * 7 + d]; }

    // l values + diag gate (row 0 of group)
    float gate[7], lv[28];
#pragma unroll
    for (int o = 0; o < 7; o++) {
        float a = Pb[1 + o] + b_ld[o];
        gate[o] = (a > 0.f) ? 1.f : 0.f;
        lv[o]   = fmaxf(a, 0.f);
    }
#pragma unroll
    for (int j = 0; j < 21; j++) lv[7 + j] = Pb[8 + j] + b_lo[j];

    // w = L^T v
    float w[7] = {0,0,0,0,0,0,0};
#pragma unroll
    for (int i = 0; i < 28; i++) w[Cc[i]] += lv[i] * v[R[i]];

    // pass over the 7 derivative rows: dldt, s (=0.5*quad_dq), G
    float dldt[28];
#pragma unroll
    for (int i = 0; i < 28; i++) dldt[i] = 0.f;
    float s[7], G[7];
#pragma unroll
    for (int d = 0; d < 7; d++) {
        const float* row = Pb + (size_t)(1 + d) * 32;
        G[d] = row[0];
        float sd = 0.f;
#pragma unroll
        for (int i = 0; i < 28; i++) {
            float e = row[1 + i];
            if (i < 7) e *= gate[i];
            dldt[i] = fmaf(e, v[d], dldt[i]);
            sd = fmaf(e, v[R[i]] * w[Cc[i]], sd);
        }
        s[d] = sd;
    }

    // p = dLdt^T v ; lw = dLdt w ; Lp = L p ; u = L^T a ; Mq = L u
    float p[7]  = {0,0,0,0,0,0,0};
    float lw[7] = {0,0,0,0,0,0,0};
#pragma unroll
    for (int i = 0; i < 28; i++) {
        p[Cc[i]]  += dldt[i] * v[R[i]];
        lw[R[i]]  += dldt[i] * w[Cc[i]];
    }
    float Lp[7] = {0,0,0,0,0,0,0};
    float u[7]  = {0,0,0,0,0,0,0};
#pragma unroll
    for (int i = 0; i < 28; i++) u[Cc[i]] += lv[i] * ac[R[i]];
    float Mq[7] = {0,0,0,0,0,0,0};
#pragma unroll
    for (int i = 0; i < 28; i++) {
        Lp[R[i]] += lv[i] * p[Cc[i]];
        Mq[R[i]] += lv[i] * u[Cc[i]];
    }

    const size_t B7 = (size_t)B * 7;
#pragma unroll
    for (int r = 0; r < 7; r++) {
        float Cr  = Lp[r] + lw[r] - s[r];
        float tau = Mq[r] + EPSR * ac[r] + Cr + G[r];
        out[(size_t)b * 7 + r]          = tau;     // tau_pred
        out[B7 * 8 + (size_t)b * 7 + r] = Cr;      // C (offset B*56)
        out[B7 * 9 + (size_t)b * 7 + r] = G[r];    // G (offset B*63)
    }

    // M = L L^T + eps I   (full 7x7) at offset B*7
    float Lm[7][7];
#pragma unroll
    for (int r = 0; r < 7; r++)
#pragma unroll
        for (int c = 0; c < 7; c++) Lm[r][c] = 0.f;
#pragma unroll
    for (int i = 0; i < 28; i++) Lm[R[i]][Cc[i]] = lv[i];

    float* Mout = out + B7 + (size_t)b * 49;
#pragma unroll
    for (int r = 0; r < 7; r++)
#pragma unroll
        for (int c = 0; c < 7; c++) {
            float m = (r == c) ? EPSR : 0.f;
#pragma unroll
            for (int t = 0; t < 7; t++) m = fmaf(Lm[r][t], Lm[c][t], m);
            Mout[r * 7 + c] = m;
        }
}

// ---------------------------------------------------------------------------
// kernel_launch — graph-capturable, allocation-free.
// Input order: state, velocity, acceleration, W_in, b_in, W_h, b_h,
//              W_g, b_g, W_ld, b_ld, W_lo, b_lo
// ---------------------------------------------------------------------------
extern "C" void kernel_launch(void* const* d_in, const int* in_sizes, int n_in,
                              void* d_out, int out_size)
{
    const float* state  = (const float*)d_in[0];
    const float* vel    = (const float*)d_in[1];
    const float* accel  = (const float*)d_in[2];
    const float* W_in   = (const float*)d_in[3];
    const float* b_in   = (const float*)d_in[4];
    const float* W_h    = (const float*)d_in[5];
    const float* b_h    = (const float*)d_in[6];
    const float* W_g    = (const float*)d_in[7];
    // d_in[8] = b_g : unused (V value never appears in outputs)
    const float* W_ld   = (const float*)d_in[9];
    const float* b_ld   = (const float*)d_in[10];
    const float* W_lo   = (const float*)d_in[11];
    const float* b_lo   = (const float*)d_in[12];

    const int B = in_sizes[0] / N_DOF;   // 8192
    const int Mrows = B * 8;             // 65536

    float *z0, *z1, *pp;
    cudaGetSymbolAddress((void**)&z0, g_Z0);
    cudaGetSymbolAddress((void**)&z1, g_Z1);
    cudaGetSymbolAddress((void**)&pp, g_P);

    // 1) input layer
    {
        int total = B * WIDTH;
        layer1_kernel<<<(total + 255) / 256, 256>>>(state, W_in, b_in, z0, B);
    }
    // 2) two fused hidden layers (ping-pong)
    {
        dim3 grid(WIDTH / 128, (Mrows + 127) / 128);
        gemm_fused_kernel<<<grid, 256>>>(z0, W_h, b_h, z1, Mrows);
        gemm_fused_kernel<<<grid, 256>>>(z1, W_h, b_h, z0, Mrows);
    }
    // 3) head projections
    proj_kernel<<<(Mrows + 63) / 64, 256>>>(z0, W_g, W_ld, W_lo, pp, Mrows);
    // 4) per-sample assembly -> d_out
    assemble_kernel<<<(B + 255) / 256, 256>>>(pp, vel, accel, b_ld, b_lo,
                                              (float*)d_out, B);
}

// round 6
// speedup vs baseline: 1.0554x; 1.0554x over previous
#include <cuda_runtime.h>
#include <cstdint>

// ---------------------------------------------------------------------------
// DeepLagrangianNetwork forward on GB300, fp32 with packed f32x2 FMA.
//   Z[b, r, :]  r=0: activations y;  r=1..7: dy/dq_{r-1}   (group of 8 rows)
//   1) layer1:   Z0 = relu(state@W_in+b), d1 = gate * W_in^T
//   2) gemm x2:  Z_{k+1} = epilogue(Z_k @ W_h)  double-buffered, fused gate
//   3) proj:     P = Z3 @ [W_g | W_ld | W_lo]   row-per-thread, f32x2
//   4) assemble: per-sample 7x7 Lagrangian algebra -> tau, M, C, G
// ---------------------------------------------------------------------------

#define N_DOF   7
#define WIDTH   1024
#define EPSR    1e-5f

__device__ float g_Z0[65536 * 1024];      // 256 MB
__device__ float g_Z1[65536 * 1024];      // 256 MB
__device__ float g_P [65536 * 32];        // 8 MB (29 cols padded to 32)

typedef unsigned long long ull;

// ---- packed f32x2 helpers (Blackwell) -------------------------------------
__device__ __forceinline__ ull dup2(float a) {
    ull r;
    asm("mov.b64 %0, {%1, %1};" : "=l"(r) : "f"(a));
    return r;
}
__device__ __forceinline__ void fma2(ull &d, ull a, ull b) {
    asm("fma.rn.f32x2 %0, %1, %2, %0;" : "+l"(d) : "l"(a), "l"(b));
}
__device__ __forceinline__ float2 unpack2(ull v) {
    float2 r;
    asm("mov.b64 {%0, %1}, %2;" : "=f"(r.x), "=f"(r.y) : "l"(v));
    return r;
}

// ---------------------------------------------------------------------------
// Kernel 1: input layer.
// ---------------------------------------------------------------------------
__global__ void __launch_bounds__(256)
layer1_kernel(const float* __restrict__ state,
              const float* __restrict__ W_in,
              const float* __restrict__ b_in,
              float* __restrict__ Z, int B)
{
    int g = blockIdx.x * blockDim.x + threadIdx.x;
    if (g >= B * WIDTH) return;
    int b = g >> 10;
    int o = g & (WIDTH - 1);

    float a = b_in[o];
    float wv[N_DOF];
#pragma unroll
    for (int i = 0; i < N_DOF; i++) {
        wv[i] = W_in[i * WIDTH + o];
        a = fmaf(state[b * N_DOF + i], wv[i], a);
    }
    size_t base = ((size_t)b * 8) * WIDTH + o;
    Z[base] = fmaxf(a, 0.f);
    float gate = (a > 0.f) ? 1.f : 0.f;
#pragma unroll
    for (int d = 0; d < N_DOF; d++)
        Z[base + (size_t)(1 + d) * WIDTH] = gate * wv[d];
}

// ---------------------------------------------------------------------------
// Kernel 2: fused hidden-layer GEMM, 2-stage double-buffered smem.
// BM=BN=128, BK=16, 256 threads, 8x8 micro-tile, f32x2 packed FMAs.
// One __syncthreads per K-tile; next tile's LDGs issued before compute.
// Assumes Mrows % 128 == 0 (true: 8192*8 = 65536).
// ---------------------------------------------------------------------------
__global__ void __launch_bounds__(256, 2)
gemm_fused_kernel(const float* __restrict__ Zin,
                  const float* __restrict__ W,
                  const float* __restrict__ bias,
                  float* __restrict__ Zout)
{
    __shared__ __align__(16) float As[2][16][128];   // As[buf][k][m]
    __shared__ __align__(16) float Bs[2][16][128];   // Bs[buf][k][n]

    const int tid = threadIdx.x;
    const int tr  = tid >> 4;        // 0..15
    const int tc  = tid & 15;        // 0..15
    const int rowBase = blockIdx.y * 128;
    const int colBase = blockIdx.x * 128;

    const float* gA = Zin + (size_t)rowBase * WIDTH;
    const float* gB = W + colBase;

    // load-index decomposition (two 256-thread passes cover each tile)
    const int aR0 = tid >> 2,          aC0 = (tid & 3) * 4;
    const int aR1 = (tid + 256) >> 2,  aC1 = ((tid + 256) & 3) * 4;
    const int bR0 = tid >> 5,          bC0 = (tid & 31) * 4;
    const int bR1 = (tid + 256) >> 5,  bC1 = ((tid + 256) & 31) * 4;

    float4 a0, a1, b0, b1;

    // ---- prologue: tile 0 ----
    a0 = *reinterpret_cast<const float4*>(&gA[(size_t)aR0 * WIDTH + aC0]);
    a1 = *reinterpret_cast<const float4*>(&gA[(size_t)aR1 * WIDTH + aC1]);
    b0 = *reinterpret_cast<const float4*>(&gB[(size_t)bR0 * WIDTH + bC0]);
    b1 = *reinterpret_cast<const float4*>(&gB[(size_t)bR1 * WIDTH + bC1]);
    As[0][aC0 + 0][aR0] = a0.x; As[0][aC0 + 1][aR0] = a0.y;
    As[0][aC0 + 2][aR0] = a0.z; As[0][aC0 + 3][aR0] = a0.w;
    As[0][aC1 + 0][aR1] = a1.x; As[0][aC1 + 1][aR1] = a1.y;
    As[0][aC1 + 2][aR1] = a1.z; As[0][aC1 + 3][aR1] = a1.w;
    *reinterpret_cast<float4*>(&Bs[0][bR0][bC0]) = b0;
    *reinterpret_cast<float4*>(&Bs[0][bR1][bC1]) = b1;
    __syncthreads();

    ull acc[8][4];
#pragma unroll
    for (int i = 0; i < 8; i++)
#pragma unroll
        for (int j = 0; j < 4; j++) acc[i][j] = 0ull;

    for (int t = 0; t < 64; t++) {
        const int p = t & 1;
        // prefetch next tile into registers (latency hidden by compute)
        if (t < 63) {
            const int kt = (t + 1) * 16;
            a0 = *reinterpret_cast<const float4*>(&gA[(size_t)aR0 * WIDTH + kt + aC0]);
            a1 = *reinterpret_cast<const float4*>(&gA[(size_t)aR1 * WIDTH + kt + aC1]);
            b0 = *reinterpret_cast<const float4*>(&gB[(size_t)(kt + bR0) * WIDTH + bC0]);
            b1 = *reinterpret_cast<const float4*>(&gB[(size_t)(kt + bR1) * WIDTH + bC1]);
        }

        const float (*Asp)[128] = As[p];
        const float (*Bsp)[128] = Bs[p];
#pragma unroll
        for (int kk = 0; kk < 16; kk++) {
            float4 A0 = *reinterpret_cast<const float4*>(&Asp[kk][tr * 8]);
            float4 A1 = *reinterpret_cast<const float4*>(&Asp[kk][tr * 8 + 4]);
            const ull* bp = reinterpret_cast<const ull*>(&Bsp[kk][tc * 8]);
            ull B0 = bp[0], B1 = bp[1], B2 = bp[2], B3 = bp[3];
            ull A2[8] = { dup2(A0.x), dup2(A0.y), dup2(A0.z), dup2(A0.w),
                          dup2(A1.x), dup2(A1.y), dup2(A1.z), dup2(A1.w) };
#pragma unroll
            for (int i = 0; i < 8; i++) {
                fma2(acc[i][0], A2[i], B0);
                fma2(acc[i][1], A2[i], B1);
                fma2(acc[i][2], A2[i], B2);
                fma2(acc[i][3], A2[i], B3);
            }
        }

        if (t < 63) {
            const int q = p ^ 1;   // other buffer is free (last read at t-1)
            As[q][aC0 + 0][aR0] = a0.x; As[q][aC0 + 1][aR0] = a0.y;
            As[q][aC0 + 2][aR0] = a0.z; As[q][aC0 + 3][aR0] = a0.w;
            As[q][aC1 + 0][aR1] = a1.x; As[q][aC1 + 1][aR1] = a1.y;
            As[q][aC1 + 2][aR1] = a1.z; As[q][aC1 + 3][aR1] = a1.w;
            *reinterpret_cast<float4*>(&Bs[q][bR0][bC0]) = b0;
            *reinterpret_cast<float4*>(&Bs[q][bR1][bC1]) = b1;
            __syncthreads();
        }
    }

    // --- epilogue: bias+relu on row 0, gate rows 1..7 with row-0 sign
    const int grow0 = rowBase + tr * 8;
    const int col0  = colBase + tc * 8;

    float yv[8], gv[8];
#pragma unroll
    for (int j2 = 0; j2 < 4; j2++) {
        float2 f = unpack2(acc[0][j2]);
        float a0f = f.x + bias[col0 + 2 * j2];
        float a1f = f.y + bias[col0 + 2 * j2 + 1];
        yv[2 * j2]     = fmaxf(a0f, 0.f);
        yv[2 * j2 + 1] = fmaxf(a1f, 0.f);
        gv[2 * j2]     = (a0f > 0.f) ? 1.f : 0.f;
        gv[2 * j2 + 1] = (a1f > 0.f) ? 1.f : 0.f;
    }
    {
        float4* p = reinterpret_cast<float4*>(&Zout[(size_t)grow0 * WIDTH + col0]);
        p[0] = make_float4(yv[0], yv[1], yv[2], yv[3]);
        p[1] = make_float4(yv[4], yv[5], yv[6], yv[7]);
    }
#pragma unroll
    for (int r = 1; r < 8; r++) {
        float ov[8];
#pragma unroll
        for (int j2 = 0; j2 < 4; j2++) {
            float2 f = unpack2(acc[r][j2]);
            ov[2 * j2]     = gv[2 * j2]     * f.x;
            ov[2 * j2 + 1] = gv[2 * j2 + 1] * f.y;
        }
        float4* p = reinterpret_cast<float4*>(&Zout[(size_t)(grow0 + r) * WIDTH + col0]);
        p[0] = make_float4(ov[0], ov[1], ov[2], ov[3]);
        p[1] = make_float4(ov[4], ov[5], ov[6], ov[7]);
    }
}

// ---------------------------------------------------------------------------
// Kernel 3 (v2): head projection. One row per thread (256 rows/block).
// Zs staged conflict-free (pad 33); W staged as 32x32 tile, read broadcast.
// f32x2-packed over column pairs. Assumes Mrows % 256 == 0.
// ---------------------------------------------------------------------------
__global__ void __launch_bounds__(256)
proj_kernel(const float* __restrict__ Z,
            const float* __restrict__ Wg,
            const float* __restrict__ Wld,
            const float* __restrict__ Wlo,
            float* __restrict__ P)
{
    __shared__ float Zs[256][33];                 // 33.0 KB, conflict-free
    __shared__ __align__(16) float Ws[32][32];    // 4 KB

    const int tid = threadIdx.x;
    const size_t rowBase = (size_t)blockIdx.x * 256;

    ull acc2[16];
#pragma unroll
    for (int q = 0; q < 16; q++) acc2[q] = 0ull;

    for (int k0 = 0; k0 < WIDTH; k0 += 32) {
        __syncthreads();  // previous chunk's reads done before overwrite
        // stage Z: 256 rows x 32 k, coalesced float4 loads, scalar STS
#pragma unroll
        for (int t = 0; t < 8; t++) {
            int lin = tid + 256 * t;
            int r   = lin >> 3;
            int c4  = (lin & 7) * 4;
            float4 v = *reinterpret_cast<const float4*>(
                &Z[(rowBase + r) * WIDTH + k0 + c4]);
            Zs[r][c4 + 0] = v.x; Zs[r][c4 + 1] = v.y;
            Zs[r][c4 + 2] = v.z; Zs[r][c4 + 3] = v.w;
        }
        // stage W: 32 k x 32 cols (29 real + 3 zero pad)
#pragma unroll
        for (int t = 0; t < 4; t++) {
            int lin = tid + 256 * t;
            int k   = lin >> 5;
            int c   = lin & 31;
            int kk  = k0 + k;
            float wv = 0.f;
            if (c == 0)      wv = Wg[kk];
            else if (c < 8)  wv = Wld[kk * 7  + (c - 1)];
            else if (c < 29) wv = Wlo[kk * 21 + (c - 8)];
            Ws[k][c] = wv;
        }
        __syncthreads();

#pragma unroll
        for (int kk = 0; kk < 32; kk++) {
            ull z2 = dup2(Zs[tid][kk]);                       // bank = tid+kk: clean
            const ull* w2 = reinterpret_cast<const ull*>(&Ws[kk][0]);  // broadcast
#pragma unroll
            for (int q = 0; q < 16; q++) fma2(acc2[q], z2, w2[q]);
        }
    }

    float4* po = reinterpret_cast<float4*>(&P[(rowBase + tid) * 32]);
#pragma unroll
    for (int q = 0; q < 8; q++) {
        float2 f0 = unpack2(acc2[2 * q]);
        float2 f1 = unpack2(acc2[2 * q + 1]);
        po[q] = make_float4(f0.x, f0.y, f1.x, f1.y);
    }
}

// ---------------------------------------------------------------------------
// Kernel 4: per-sample Lagrangian assembly (unchanged algebra).
// Output: tau [B,7] | M [B,7,7] | C [B,7] | G [B,7]
// ---------------------------------------------------------------------------
__global__ void __launch_bounds__(256)
assemble_kernel(const float* __restrict__ P,
                const float* __restrict__ vel,
                const float* __restrict__ accel,
                const float* __restrict__ b_ld,
                const float* __restrict__ b_lo,
                float* __restrict__ out, int B)
{
    int b = blockIdx.x * blockDim.x + threadIdx.x;
    if (b >= B) return;

    constexpr int R[28] = {0,1,2,3,4,5,6, 1,2,3,4,5,6, 2,3,4,5,6, 3,4,5,6, 4,5,6, 5,6, 6};
    constexpr int Cc[28]= {0,1,2,3,4,5,6, 0,1,2,3,4,5, 0,1,2,3,4, 0,1,2,3, 0,1,2, 0,1, 0};

    const float* Pb = P + (size_t)b * 256;

    float v[7], ac[7];
#pragma unroll
    for (int d = 0; d < 7; d++) { v[d] = vel[b * 7 + d]; ac[d] = accel[b * 7 + d]; }

    float gate[7], lv[28];
#pragma unroll
    for (int o = 0; o < 7; o++) {
        float a = Pb[1 + o] + b_ld[o];
        gate[o] = (a > 0.f) ? 1.f : 0.f;
        lv[o]   = fmaxf(a, 0.f);
    }
#pragma unroll
    for (int j = 0; j < 21; j++) lv[7 + j] = Pb[8 + j] + b_lo[j];

    float w[7] = {0,0,0,0,0,0,0};
#pragma unroll
    for (int i = 0; i < 28; i++) w[Cc[i]] += lv[i] * v[R[i]];

    float dldt[28];
#pragma unroll
    for (int i = 0; i < 28; i++) dldt[i] = 0.f;
    float s[7], G[7];
#pragma unroll
    for (int d = 0; d < 7; d++) {
        const float* row = Pb + (size_t)(1 + d) * 32;
        G[d] = row[0];
        float sd = 0.f;
#pragma unroll
        for (int i = 0; i < 28; i++) {
            float e = row[1 + i];
            if (i < 7) e *= gate[i];
            dldt[i] = fmaf(e, v[d], dldt[i]);
            sd = fmaf(e, v[R[i]] * w[Cc[i]], sd);
        }
        s[d] = sd;
    }

    float p[7]  = {0,0,0,0,0,0,0};
    float lw[7] = {0,0,0,0,0,0,0};
#pragma unroll
    for (int i = 0; i < 28; i++) {
        p[Cc[i]]  += dldt[i] * v[R[i]];
        lw[R[i]]  += dldt[i] * w[Cc[i]];
    }
    float Lp[7] = {0,0,0,0,0,0,0};
    float u[7]  = {0,0,0,0,0,0,0};
#pragma unroll
    for (int i = 0; i < 28; i++) u[Cc[i]] += lv[i] * ac[R[i]];
    float Mq[7] = {0,0,0,0,0,0,0};
#pragma unroll
    for (int i = 0; i < 28; i++) {
        Lp[R[i]] += lv[i] * p[Cc[i]];
        Mq[R[i]] += lv[i] * u[Cc[i]];
    }

    const size_t B7 = (size_t)B * 7;
#pragma unroll
    for (int r = 0; r < 7; r++) {
        float Cr  = Lp[r] + lw[r] - s[r];
        float tau = Mq[r] + EPSR * ac[r] + Cr + G[r];
        out[(size_t)b * 7 + r]          = tau;
        out[B7 * 8 + (size_t)b * 7 + r] = Cr;
        out[B7 * 9 + (size_t)b * 7 + r] = G[r];
    }

    float Lm[7][7];
#pragma unroll
    for (int r = 0; r < 7; r++)
#pragma unroll
        for (int c = 0; c < 7; c++) Lm[r][c] = 0.f;
#pragma unroll
    for (int i = 0; i < 28; i++) Lm[R[i]][Cc[i]] = lv[i];

    float* Mout = out + B7 + (size_t)b * 49;
#pragma unroll
    for (int r = 0; r < 7; r++)
#pragma unroll
        for (int c = 0; c < 7; c++) {
            float m = (r == c) ? EPSR : 0.f;
#pragma unroll
            for (int t = 0; t < 7; t++) m = fmaf(Lm[r][t], Lm[c][t], m);
            Mout[r * 7 + c] = m;
        }
}

// ---------------------------------------------------------------------------
// kernel_launch — graph-capturable, allocation-free.
// ---------------------------------------------------------------------------
extern "C" void kernel_launch(void* const* d_in, const int* in_sizes, int n_in,
                              void* d_out, int out_size)
{
    const float* state  = (const float*)d_in[0];
    const float* vel    = (const float*)d_in[1];
    const float* accel  = (const float*)d_in[2];
    const float* W_in   = (const float*)d_in[3];
    const float* b_in   = (const float*)d_in[4];
    const float* W_h    = (const float*)d_in[5];
    const float* b_h    = (const float*)d_in[6];
    const float* W_g    = (const float*)d_in[7];
    // d_in[8] = b_g : unused (V never appears in outputs)
    const float* W_ld   = (const float*)d_in[9];
    const float* b_ld   = (const float*)d_in[10];
    const float* W_lo   = (const float*)d_in[11];
    const float* b_lo   = (const float*)d_in[12];

    const int B = in_sizes[0] / N_DOF;   // 8192
    const int Mrows = B * 8;             // 65536

    float *z0, *z1, *pp;
    cudaGetSymbolAddress((void**)&z0, g_Z0);
    cudaGetSymbolAddress((void**)&z1, g_Z1);
    cudaGetSymbolAddress((void**)&pp, g_P);

    // 1) input layer
    {
        int total = B * WIDTH;
        layer1_kernel<<<(total + 255) / 256, 256>>>(state, W_in, b_in, z0, B);
    }
    // 2) two fused hidden layers (ping-pong), double-buffered GEMM
    {
        dim3 grid(WIDTH / 128, Mrows / 128);
        gemm_fused_kernel<<<grid, 256>>>(z0, W_h, b_h, z1);
        gemm_fused_kernel<<<grid, 256>>>(z1, W_h, b_h, z0);
    }
    // 3) head projections
    proj_kernel<<<Mrows / 256, 256>>>(z0, W_g, W_ld, W_lo, pp);
    // 4) per-sample assembly -> d_out
    assemble_kernel<<<(B + 255) / 256, 256>>>(pp, vel, accel, b_ld, b_lo,
                                              (float*)d_out, B);
}